// round 2
// baseline (speedup 1.0000x reference)
#include <cuda_runtime.h>

// Problem constants (fixed by the reference)
#define Bsz      2048
#define Tlen     200
#define Fdim     128
#define Hdim     256
#define Odim     6
#define G4H      1024      // 4*H
#define BB       16        // batch rows per block
#define NTHREADS 256
#define PAD      18        // k-major SMEM row stride (floats): 72B rows -> 8B-aligned pairs
#define NBLK     (Bsz / BB)

typedef unsigned long long ull;

// ---------------------------------------------------------------------------
// Persistent device scratch (no allocations allowed): gate-permuted weights.
// Layout: Wp[k][4*n + g] = W[k][g*256 + n]   (g: 0=i, 1=j, 2=f, 3=o)
// +2 pad rows so the software-pipelined prefetch never reads OOB.
// ---------------------------------------------------------------------------
__device__ float g_W1p[(Fdim + Hdim + 2) * G4H];     // 386*1024
__device__ float g_W2p[(2 * Hdim + 2) * G4H];        // 514*1024
__device__ float g_b1p[G4H];
__device__ float g_b2p[G4H];

__global__ void permute_kernel(const float* __restrict__ W,
                               const float* __restrict__ b,
                               int K, int which)
{
    float* Wp = which ? g_W2p : g_W1p;
    float* bp = which ? g_b2p : g_b1p;
    int idx = blockIdx.x * blockDim.x + threadIdx.x;
    int total = K * G4H;
    if (idx < total) {
        int k = idx >> 10, c = idx & 1023;
        int n = c >> 2,  g = c & 3;
        Wp[idx] = W[(k << 10) + (g << 8) + n];
    } else if (idx < total + 2 * G4H) {
        Wp[idx] = 0.0f;                    // prefetch pad rows
    }
    if (idx < G4H) {
        int n = idx >> 2, g = idx & 3;
        bp[idx] = b[(g << 8) + n];
    }
}

// ---------------------------------------------------------------------------
// Tiny helpers
// ---------------------------------------------------------------------------
__device__ __forceinline__ ull fma2(ull a, ull b, ull c) {
    ull d;
    asm("fma.rn.f32x2 %0, %1, %2, %3;" : "=l"(d) : "l"(a), "l"(b), "l"(c));
    return d;
}
__device__ __forceinline__ ull dupf(float x) {
    ull d;
    asm("mov.b64 %0, {%1, %1};" : "=l"(d) : "f"(x));
    return d;
}
__device__ __forceinline__ float2 unpk(ull a) {
    float lo, hi;
    asm("mov.b64 {%0, %1}, %2;" : "=f"(lo), "=f"(hi) : "l"(a));
    return make_float2(lo, hi);
}
__device__ __forceinline__ ull lds64(unsigned a) {
    ull v;
    asm volatile("ld.shared.b64 %0, [%1];" : "=l"(v) : "r"(a));
    return v;
}
__device__ __forceinline__ float ex2f(float x) {
    float y; asm("ex2.approx.f32 %0, %1;" : "=f"(y) : "f"(x)); return y;
}
__device__ __forceinline__ float rcpf(float x) {
    float y; asm("rcp.approx.f32 %0, %1;" : "=f"(y) : "f"(x)); return y;
}
__device__ __forceinline__ float sigm(float x) {
    // 1/(1+exp(-x)); MUFU EX2+RCP, abs err ~1e-6, saturates correctly at +/-inf
    return rcpf(1.0f + ex2f(-1.4426950408889634f * x));
}
__device__ __forceinline__ float tanhx(float x) {
    // 2/(1+exp(-2x)) - 1
    return fmaf(2.0f, rcpf(1.0f + ex2f(-2.8853900817779268f * x)), -1.0f);
}

// ---------------------------------------------------------------------------
// Rank-1-update GEMM slice: for this thread's 4 gate columns (4*tid..4*tid+3),
// accumulate over K input features. Inputs staged k-major in SMEM, row pairs
// read as packed f32x2. Weight rows prefetched 2 deep to cover L2 latency.
//   w: &Wp4[row0*256 + tid]   (float4 units; row k at w + k*256)
//   s: shared 32-bit address of k-major buffer (stride PAD floats)
// ---------------------------------------------------------------------------
__device__ __forceinline__ void gemm_acc(const float4* __restrict__ w,
                                         unsigned s, int K, ull acc[4][8])
{
    float4 w0 = __ldg(w);
    float4 w1 = __ldg(w + 256);
#pragma unroll 2
    for (int k = 0; k < K; ++k) {
        float4 wn = __ldg(w + (k + 2) * 256);     // pad rows make this safe
        ull d0 = dupf(w0.x), d1 = dupf(w0.y), d2 = dupf(w0.z), d3 = dupf(w0.w);
        unsigned sk = s + (unsigned)(k * PAD * 4);
#pragma unroll
        for (int p = 0; p < 8; ++p) {
            ull a = lds64(sk + p * 8);            // rows (2p, 2p+1) packed
            acc[0][p] = fma2(a, d0, acc[0][p]);
            acc[1][p] = fma2(a, d1, acc[1][p]);
            acc[2][p] = fma2(a, d2, acc[2][p]);
            acc[3][p] = fma2(a, d3, acc[3][p]);
        }
        w0 = w1; w1 = wn;
    }
}

// ---------------------------------------------------------------------------
// Main persistent kernel: one block = 16 batch rows through all timesteps.
// Thread tid owns h-index n=tid (its 4 gates) for all 16 rows.
// ---------------------------------------------------------------------------
__global__ __launch_bounds__(NTHREADS, 1)
void lstm_kernel(const float* __restrict__ x, const int* __restrict__ lengths,
                 const float* __restrict__ Wout, const float* __restrict__ bout,
                 float* __restrict__ out)
{
    // __align__(16): gemm_acc uses ld.shared.b64; base must be 8B-aligned
    // (offsets are all 8B multiples: PAD=18 floats = 72B row stride).
    __shared__ __align__(16) float x_s[Fdim * PAD];    // k-major: x_s[k*PAD + r]
    __shared__ __align__(16) float h1_s[Hdim * PAD];   // k-major: h1_s[n*PAD + r]
    __shared__ __align__(16) float h2_s[Hdim * PAD];
    __shared__ int   len_s[BB];
    __shared__ int   tmax_s;

    const int tid = threadIdx.x;
    const int blk = blockIdx.x;

    for (int i = tid; i < Hdim * PAD; i += NTHREADS) { h1_s[i] = 0.0f; h2_s[i] = 0.0f; }
    if (tid < BB) len_s[tid] = lengths[blk * BB + tid];
    __syncthreads();
    if (tid == 0) {
        int m = 0;
        for (int r = 0; r < BB; ++r) m = max(m, len_s[r]);
        tmax_s = m;
    }
    __syncthreads();
    const int tmax = tmax_s;

    const unsigned xsa = (unsigned)__cvta_generic_to_shared(x_s);
    const unsigned h1a = (unsigned)__cvta_generic_to_shared(h1_s);
    const unsigned h2a = (unsigned)__cvta_generic_to_shared(h2_s);

    const float4* W1p4 = reinterpret_cast<const float4*>(g_W1p);
    const float4* W2p4 = reinterpret_cast<const float4*>(g_W2p);
    const float4  b1v  = reinterpret_cast<const float4*>(g_b1p)[tid];
    const float4  b2v  = reinterpret_cast<const float4*>(g_b2p)[tid];

    float c1[BB], c2[BB], sum[BB];
#pragma unroll
    for (int r = 0; r < BB; ++r) { c1[r] = 0.0f; c2[r] = 0.0f; sum[r] = 0.0f; }

    const int kx = tid & 127;      // x staging: this thread's feature index
    const int ph = tid >> 7;       // and which row-pair parity it covers

    for (int t = 0; t < tmax; ++t) {
        // ---- stage x_t into k-major SMEM (coalesced global reads) ----
#pragma unroll
        for (int j = 0; j < 4; ++j) {
            int p = ph + 2 * j;    // row pair 0..7
            const float* xr0 = x + (size_t)(blk * BB + 2 * p) * (Tlen * Fdim) + t * Fdim + kx;
            float a0 = __ldg(xr0);
            float a1 = __ldg(xr0 + Tlen * Fdim);
            x_s[kx * PAD + 2 * p]     = a0;
            x_s[kx * PAD + 2 * p + 1] = a1;
        }
        __syncthreads();                       // x ready, prev-step h2 visible

        // ---- layer 1 GEMM: z = [x_t | h1] @ W1p + b1p ----
        ull acc[4][8];
#pragma unroll
        for (int p = 0; p < 8; ++p) {
            acc[0][p] = dupf(b1v.x); acc[1][p] = dupf(b1v.y);
            acc[2][p] = dupf(b1v.z); acc[3][p] = dupf(b1v.w);
        }
        gemm_acc(W1p4 + tid,              xsa, Fdim, acc);
        gemm_acc(W1p4 + Fdim * 256 + tid, h1a, Hdim, acc);
        __syncthreads();                       // everyone done reading h1_s

        // ---- layer 1 cell update (all in registers; n = tid) ----
#pragma unroll
        for (int p = 0; p < 8; ++p) {
            float2 iv = unpk(acc[0][p]), jv = unpk(acc[1][p]);
            float2 fv = unpk(acc[2][p]), ov = unpk(acc[3][p]);
            {
                int r = 2 * p;
                if (t < len_s[r]) {
                    float nc = c1[r] * sigm(fv.x + 1.0f) + sigm(iv.x) * tanhx(jv.x);
                    c1[r] = nc;
                    h1_s[tid * PAD + r] = tanhx(nc) * sigm(ov.x);
                }
            }
            {
                int r = 2 * p + 1;
                if (t < len_s[r]) {
                    float nc = c1[r] * sigm(fv.y + 1.0f) + sigm(iv.y) * tanhx(jv.y);
                    c1[r] = nc;
                    h1_s[tid * PAD + r] = tanhx(nc) * sigm(ov.y);
                }
            }
        }
        __syncthreads();                       // new h1 visible

        // ---- layer 2 GEMM: z = [h1 | h2] @ W2p + b2p ----
#pragma unroll
        for (int p = 0; p < 8; ++p) {
            acc[0][p] = dupf(b2v.x); acc[1][p] = dupf(b2v.y);
            acc[2][p] = dupf(b2v.z); acc[3][p] = dupf(b2v.w);
        }
        gemm_acc(W2p4 + tid,              h1a, Hdim, acc);
        gemm_acc(W2p4 + Hdim * 256 + tid, h2a, Hdim, acc);
        __syncthreads();                       // everyone done reading h2_s

        // ---- layer 2 cell update + masked output accumulation ----
#pragma unroll
        for (int p = 0; p < 8; ++p) {
            float2 iv = unpk(acc[0][p]), jv = unpk(acc[1][p]);
            float2 fv = unpk(acc[2][p]), ov = unpk(acc[3][p]);
            {
                int r = 2 * p;
                if (t < len_s[r]) {
                    float nc = c2[r] * sigm(fv.x + 1.0f) + sigm(iv.x) * tanhx(jv.x);
                    c2[r] = nc;
                    float nh = tanhx(nc) * sigm(ov.x);
                    h2_s[tid * PAD + r] = nh;
                    sum[r] += nh;
                }
            }
            {
                int r = 2 * p + 1;
                if (t < len_s[r]) {
                    float nc = c2[r] * sigm(fv.y + 1.0f) + sigm(iv.y) * tanhx(jv.y);
                    c2[r] = nc;
                    float nh = tanhx(nc) * sigm(ov.y);
                    h2_s[tid * PAD + r] = nh;
                    sum[r] += nh;
                }
            }
        }
        // no barrier needed here: next-iter barriers order h2 writes vs reads
    }

    // ---- epilogue: avg over valid steps, project to O=6 logits ----
#pragma unroll
    for (int r = 0; r < BB; ++r)
        h1_s[tid * PAD + r] = sum[r] / (float)len_s[r];   // reuse h1_s as scratch
    __syncthreads();

    if (tid < BB * Odim) {
        int r = tid / Odim, o = tid % Odim;
        float a = __ldg(&bout[o]);
        for (int n = 0; n < Hdim; ++n)
            a += h1_s[n * PAD + r] * __ldg(&Wout[n * Odim + o]);
        out[(blk * BB + r) * Odim + o] = a;
    }
}

// ---------------------------------------------------------------------------
// Launch
// ---------------------------------------------------------------------------
extern "C" void kernel_launch(void* const* d_in, const int* in_sizes, int n_in,
                              void* d_out, int out_size)
{
    const float* x       = (const float*)d_in[0];
    const int*   lengths = (const int*)  d_in[1];
    const float* W1      = (const float*)d_in[2];
    const float* b1      = (const float*)d_in[3];
    const float* W2      = (const float*)d_in[4];
    const float* b2      = (const float*)d_in[5];
    const float* Wout    = (const float*)d_in[6];
    const float* bout    = (const float*)d_in[7];
    float*       out     = (float*)d_out;

    // Gate-permute weights into device scratch (deterministic, re-run per call)
    permute_kernel<<<(Fdim + Hdim + 2) * G4H / NTHREADS, NTHREADS>>>(W1, b1, Fdim + Hdim, 0);
    permute_kernel<<<(2 * Hdim + 2) * G4H / NTHREADS, NTHREADS>>>(W2, b2, 2 * Hdim, 1);

    lstm_kernel<<<NBLK, NTHREADS>>>(x, lengths, Wout, bout, out);
}

// round 4
// speedup vs baseline: 1.3031x; 1.3031x over previous
#include <cuda_runtime.h>

// Problem constants (fixed by the reference)
#define Bsz      2048
#define Tlen     200
#define Fdim     128
#define Hdim     256
#define Odim     6
#define G4H      1024      // 4*H
#define BB       14        // batch rows per block (147 blocks -> one wave on 148 SMs)
#define NTHREADS 256
#define PAD      14        // k-major SMEM row stride (floats); even -> 8B-aligned row pairs
#define NBLK     ((Bsz + BB - 1) / BB)   // 147
#define PF       4         // weight prefetch depth (covers ~4*112 cyc >> L2 latency)

typedef unsigned long long ull;

// ---------------------------------------------------------------------------
// Persistent device scratch (no allocations allowed): gate-permuted weights.
// Layout: Wp[k][4*n + g] = W[k][g*256 + n]   (g: 0=i, 1=j, 2=f, 3=o)
// +PF pad rows of zeros so the prefetch ring never reads OOB.
// ---------------------------------------------------------------------------
__device__ float g_W1p[(Fdim + Hdim + PF) * G4H];
__device__ float g_W2p[(2 * Hdim + PF) * G4H];
__device__ float g_b1p[G4H];
__device__ float g_b2p[G4H];

__global__ void permute_kernel(const float* __restrict__ W,
                               const float* __restrict__ b,
                               int K, int which)
{
    float* Wp = which ? g_W2p : g_W1p;
    float* bp = which ? g_b2p : g_b1p;
    int idx = blockIdx.x * blockDim.x + threadIdx.x;
    int total = K * G4H;
    if (idx < total) {
        int k = idx >> 10, c = idx & 1023;
        int n = c >> 2,  g = c & 3;
        Wp[idx] = W[(k << 10) + (g << 8) + n];
    } else if (idx < total + PF * G4H) {
        Wp[idx] = 0.0f;                    // prefetch pad rows
    }
    if (idx < G4H) {
        int n = idx >> 2, g = idx & 3;
        bp[idx] = b[(g << 8) + n];
    }
}

// ---------------------------------------------------------------------------
// Tiny helpers
// ---------------------------------------------------------------------------
__device__ __forceinline__ ull fma2(ull a, ull b, ull c) {
    ull d;
    asm("fma.rn.f32x2 %0, %1, %2, %3;" : "=l"(d) : "l"(a), "l"(b), "l"(c));
    return d;
}
__device__ __forceinline__ ull dupf(float x) {
    ull d;
    asm("mov.b64 %0, {%1, %1};" : "=l"(d) : "f"(x));
    return d;
}
__device__ __forceinline__ float2 unpk(ull a) {
    float lo, hi;
    asm("mov.b64 {%0, %1}, %2;" : "=f"(lo), "=f"(hi) : "l"(a));
    return make_float2(lo, hi);
}
__device__ __forceinline__ ull lds64(unsigned a) {
    ull v;
    asm volatile("ld.shared.b64 %0, [%1];" : "=l"(v) : "r"(a));
    return v;
}
__device__ __forceinline__ float ex2f(float x) {
    float y; asm("ex2.approx.f32 %0, %1;" : "=f"(y) : "f"(x)); return y;
}
__device__ __forceinline__ float rcpf(float x) {
    float y; asm("rcp.approx.f32 %0, %1;" : "=f"(y) : "f"(x)); return y;
}
__device__ __forceinline__ float sigm(float x) {
    // 1/(1+exp(-x)); MUFU EX2+RCP, abs err ~1e-6, saturates correctly at +/-inf
    return rcpf(1.0f + ex2f(-1.4426950408889634f * x));
}
__device__ __forceinline__ float tanhx(float x) {
    // 2/(1+exp(-2x)) - 1
    return fmaf(2.0f, rcpf(1.0f + ex2f(-2.8853900817779268f * x)), -1.0f);
}

// ---------------------------------------------------------------------------
// Rank-1-update GEMM slice: for this thread's 4 gate columns (4*tid..4*tid+3),
// accumulate over K input features. Inputs staged k-major in SMEM, row pairs
// read as packed f32x2 (broadcast loads: all threads read the same address).
// Weight rows prefetched PF=4 deep in a register ring to cover L2 latency.
//   w: &Wp4[row0*256 + tid]   (float4 units; row k at w + k*256)
//   s: shared 32-bit address of k-major buffer (stride PAD floats)
// ---------------------------------------------------------------------------
__device__ __forceinline__ void gemm_acc(const float4* __restrict__ w,
                                         unsigned s, int K, ull acc[4][7])
{
    float4 wb0 = __ldg(w);
    float4 wb1 = __ldg(w + 256);
    float4 wb2 = __ldg(w + 2 * 256);
    float4 wb3 = __ldg(w + 3 * 256);
#pragma unroll 4
    for (int k = 0; k < K; ++k) {
        float4 wc = wb0;
        wb0 = wb1; wb1 = wb2; wb2 = wb3;
        wb3 = __ldg(w + (k + PF) * 256);          // pad rows make this safe
        ull d0 = dupf(wc.x), d1 = dupf(wc.y), d2 = dupf(wc.z), d3 = dupf(wc.w);
        unsigned sk = s + (unsigned)(k * PAD * 4);
#pragma unroll
        for (int p = 0; p < 7; ++p) {
            ull a = lds64(sk + p * 8);            // rows (2p, 2p+1) packed
            acc[0][p] = fma2(a, d0, acc[0][p]);
            acc[1][p] = fma2(a, d1, acc[1][p]);
            acc[2][p] = fma2(a, d2, acc[2][p]);
            acc[3][p] = fma2(a, d3, acc[3][p]);
        }
    }
}

// ---------------------------------------------------------------------------
// Main persistent kernel: one block = 14 batch rows through all timesteps.
// Thread tid owns h-index n=tid (its 4 gates) for all 14 rows.
// ---------------------------------------------------------------------------
__global__ __launch_bounds__(NTHREADS, 1)
void lstm_kernel(const float* __restrict__ x, const int* __restrict__ lengths,
                 const float* __restrict__ Wout, const float* __restrict__ bout,
                 float* __restrict__ out)
{
    // __align__(16): gemm_acc uses ld.shared.b64; offsets are 8B multiples
    // (PAD=14 floats = 56B row stride, pair offsets 8B).
    __shared__ __align__(16) float x_s[Fdim * PAD];    // k-major: x_s[k*PAD + r]
    __shared__ __align__(16) float h1_s[Hdim * PAD];   // k-major: h1_s[n*PAD + r]
    __shared__ __align__(16) float h2_s[Hdim * PAD];
    __shared__ int   len_s[BB];
    __shared__ int   tmax_s;

    const int tid = threadIdx.x;
    const int blk = blockIdx.x;

    for (int i = tid; i < Hdim * PAD; i += NTHREADS) { h1_s[i] = 0.0f; h2_s[i] = 0.0f; }
    if (tid < BB) {
        int row = blk * BB + tid;
        len_s[tid] = (row < Bsz) ? lengths[row] : 0;   // edge block: mask dead rows
    }
    __syncthreads();
    if (tid == 0) {
        int m = 0;
        for (int r = 0; r < BB; ++r) m = max(m, len_s[r]);
        tmax_s = m;
    }
    __syncthreads();
    const int tmax = tmax_s;

    const unsigned xsa = (unsigned)__cvta_generic_to_shared(x_s);
    const unsigned h1a = (unsigned)__cvta_generic_to_shared(h1_s);
    const unsigned h2a = (unsigned)__cvta_generic_to_shared(h2_s);

    const float4* W1p4 = reinterpret_cast<const float4*>(g_W1p);
    const float4* W2p4 = reinterpret_cast<const float4*>(g_W2p);
    const float4  b1v  = reinterpret_cast<const float4*>(g_b1p)[tid];
    const float4  b2v  = reinterpret_cast<const float4*>(g_b2p)[tid];

    float c1[BB], c2[BB], sum[BB];
#pragma unroll
    for (int r = 0; r < BB; ++r) { c1[r] = 0.0f; c2[r] = 0.0f; sum[r] = 0.0f; }

    const int kx = tid & 127;      // x staging: this thread's feature index
    const int ph = tid >> 7;       // row parity this thread covers

    for (int t = 0; t < tmax; ++t) {
        // ---- stage x_t into k-major SMEM (coalesced global reads) ----
#pragma unroll
        for (int j = 0; j < 7; ++j) {
            int r = 2 * j + ph;                       // rows 0..13
            int row_g = min(blk * BB + r, Bsz - 1);   // clamp dead rows (masked anyway)
            x_s[kx * PAD + r] =
                __ldg(x + (size_t)row_g * (Tlen * Fdim) + t * Fdim + kx);
        }
        __syncthreads();                       // x ready, prev-step h2 visible

        // ---- layer 1 GEMM: z = [x_t | h1] @ W1p + b1p ----
        ull acc[4][7];
#pragma unroll
        for (int p = 0; p < 7; ++p) {
            acc[0][p] = dupf(b1v.x); acc[1][p] = dupf(b1v.y);
            acc[2][p] = dupf(b1v.z); acc[3][p] = dupf(b1v.w);
        }
        gemm_acc(W1p4 + tid,              xsa, Fdim, acc);
        gemm_acc(W1p4 + Fdim * 256 + tid, h1a, Hdim, acc);
        __syncthreads();                       // everyone done reading h1_s

        // ---- layer 1 cell update (all in registers; n = tid) ----
#pragma unroll
        for (int p = 0; p < 7; ++p) {
            float2 iv = unpk(acc[0][p]), jv = unpk(acc[1][p]);
            float2 fv = unpk(acc[2][p]), ov = unpk(acc[3][p]);
            {
                int r = 2 * p;
                if (t < len_s[r]) {
                    float nc = c1[r] * sigm(fv.x + 1.0f) + sigm(iv.x) * tanhx(jv.x);
                    c1[r] = nc;
                    h1_s[tid * PAD + r] = tanhx(nc) * sigm(ov.x);
                }
            }
            {
                int r = 2 * p + 1;
                if (t < len_s[r]) {
                    float nc = c1[r] * sigm(fv.y + 1.0f) + sigm(iv.y) * tanhx(jv.y);
                    c1[r] = nc;
                    h1_s[tid * PAD + r] = tanhx(nc) * sigm(ov.y);
                }
            }
        }
        __syncthreads();                       // new h1 visible

        // ---- layer 2 GEMM: z = [h1 | h2] @ W2p + b2p ----
#pragma unroll
        for (int p = 0; p < 7; ++p) {
            acc[0][p] = dupf(b2v.x); acc[1][p] = dupf(b2v.y);
            acc[2][p] = dupf(b2v.z); acc[3][p] = dupf(b2v.w);
        }
        gemm_acc(W2p4 + tid,              h1a, Hdim, acc);
        gemm_acc(W2p4 + Hdim * 256 + tid, h2a, Hdim, acc);
        __syncthreads();                       // everyone done reading h2_s

        // ---- layer 2 cell update + masked output accumulation ----
#pragma unroll
        for (int p = 0; p < 7; ++p) {
            float2 iv = unpk(acc[0][p]), jv = unpk(acc[1][p]);
            float2 fv = unpk(acc[2][p]), ov = unpk(acc[3][p]);
            {
                int r = 2 * p;
                if (t < len_s[r]) {
                    float nc = c2[r] * sigm(fv.x + 1.0f) + sigm(iv.x) * tanhx(jv.x);
                    c2[r] = nc;
                    float nh = tanhx(nc) * sigm(ov.x);
                    h2_s[tid * PAD + r] = nh;
                    sum[r] += nh;
                }
            }
            {
                int r = 2 * p + 1;
                if (t < len_s[r]) {
                    float nc = c2[r] * sigm(fv.y + 1.0f) + sigm(iv.y) * tanhx(jv.y);
                    c2[r] = nc;
                    float nh = tanhx(nc) * sigm(ov.y);
                    h2_s[tid * PAD + r] = nh;
                    sum[r] += nh;
                }
            }
        }
        // no barrier needed here: next-iter barriers order h2 writes vs reads
    }

    // ---- epilogue: avg over valid steps, project to O=6 logits ----
#pragma unroll
    for (int r = 0; r < BB; ++r)
        h1_s[tid * PAD + r] = sum[r] / (float)len_s[r];   // reuse h1_s as scratch
    __syncthreads();

    if (tid < BB * Odim) {
        int r = tid / Odim, o = tid % Odim;
        int row_g = blk * BB + r;
        if (row_g < Bsz) {
            float a = __ldg(&bout[o]);
            for (int n = 0; n < Hdim; ++n)
                a += h1_s[n * PAD + r] * __ldg(&Wout[n * Odim + o]);
            out[row_g * Odim + o] = a;
        }
    }
}

// ---------------------------------------------------------------------------
// Launch
// ---------------------------------------------------------------------------
extern "C" void kernel_launch(void* const* d_in, const int* in_sizes, int n_in,
                              void* d_out, int out_size)
{
    const float* x       = (const float*)d_in[0];
    const int*   lengths = (const int*)  d_in[1];
    const float* W1      = (const float*)d_in[2];
    const float* b1      = (const float*)d_in[3];
    const float* W2      = (const float*)d_in[4];
    const float* b2      = (const float*)d_in[5];
    const float* Wout    = (const float*)d_in[6];
    const float* bout    = (const float*)d_in[7];
    float*       out     = (float*)d_out;

    // Gate-permute weights into device scratch (deterministic, re-run per call)
    permute_kernel<<<((Fdim + Hdim + PF) * G4H + NTHREADS - 1) / NTHREADS, NTHREADS>>>(
        W1, b1, Fdim + Hdim, 0);
    permute_kernel<<<((2 * Hdim + PF) * G4H + NTHREADS - 1) / NTHREADS, NTHREADS>>>(
        W2, b2, 2 * Hdim, 1);

    lstm_kernel<<<NBLK, NTHREADS>>>(x, lengths, Wout, bout, out);
}

// round 6
// speedup vs baseline: 1.8458x; 1.4165x over previous
#include <cuda_runtime.h>

// Problem constants (fixed by the reference)
#define Bsz      2048
#define Tlen     200
#define Fdim     128
#define Hdim     256
#define Odim     6
#define G4H      1024      // 4*H
#define BB       8         // batch rows per group (256 groups, length-sorted)
#define NGRP     (Bsz / BB)          // 256
#define NTHREADS 256
#define PAD      10        // k-major SMEM row stride (floats); even -> 8B pairs; 2-way bank conflicts only
#define NSM      148       // one block per SM, static LPT schedule
#define NSINGLE  (2 * NSM - NGRP)    // 40 blocks carry a single (longest) group
#define PF       4         // weight prefetch ring depth

typedef unsigned long long ull;

// ---------------------------------------------------------------------------
// Persistent device scratch (no allocations allowed)
// ---------------------------------------------------------------------------
__device__ float g_W1p[(Fdim + Hdim + PF) * G4H];
__device__ float g_W2p[(2 * Hdim + PF) * G4H];
__device__ float g_b1p[G4H];
__device__ float g_b2p[G4H];
__device__ int   g_perm[Bsz];        // row indices sorted by length DESCENDING

// Gate-permute weights: Wp[k][4*n + g] = W[k][g*256 + n]; +PF zero pad rows.
__global__ void permute_kernel(const float* __restrict__ W,
                               const float* __restrict__ b,
                               int K, int which)
{
    float* Wp = which ? g_W2p : g_W1p;
    float* bp = which ? g_b2p : g_b1p;
    int idx = blockIdx.x * blockDim.x + threadIdx.x;
    int total = K * G4H;
    if (idx < total) {
        int k = idx >> 10, c = idx & 1023;
        int n = c >> 2,  g = c & 3;
        Wp[idx] = W[(k << 10) + (g << 8) + n];
    } else if (idx < total + PF * G4H) {
        Wp[idx] = 0.0f;
    }
    if (idx < G4H) {
        int n = idx >> 2, g = idx & 3;
        bp[idx] = b[(g << 8) + n];
    }
}

// Deterministic descending sort by (length, index): rank via full scan.
__global__ void rank_kernel(const int* __restrict__ lengths)
{
    int i = blockIdx.x * blockDim.x + threadIdx.x;   // 0..2047
    int li = lengths[i];
    int rank = 0;
    for (int j = 0; j < Bsz; ++j) {
        int lj = __ldg(&lengths[j]);
        rank += (lj > li) || (lj == li && j < i);
    }
    g_perm[rank] = i;
}

// ---------------------------------------------------------------------------
// Tiny helpers
// ---------------------------------------------------------------------------
__device__ __forceinline__ ull fma2(ull a, ull b, ull c) {
    ull d;
    asm("fma.rn.f32x2 %0, %1, %2, %3;" : "=l"(d) : "l"(a), "l"(b), "l"(c));
    return d;
}
__device__ __forceinline__ ull dupf(float x) {
    ull d;
    asm("mov.b64 %0, {%1, %1};" : "=l"(d) : "f"(x));
    return d;
}
__device__ __forceinline__ float2 unpk(ull a) {
    float lo, hi;
    asm("mov.b64 {%0, %1}, %2;" : "=f"(lo), "=f"(hi) : "l"(a));
    return make_float2(lo, hi);
}
__device__ __forceinline__ ull lds64(unsigned a) {
    ull v;
    asm volatile("ld.shared.b64 %0, [%1];" : "=l"(v) : "r"(a));
    return v;
}
__device__ __forceinline__ float ex2f(float x) {
    float y; asm("ex2.approx.f32 %0, %1;" : "=f"(y) : "f"(x)); return y;
}
__device__ __forceinline__ float rcpf(float x) {
    float y; asm("rcp.approx.f32 %0, %1;" : "=f"(y) : "f"(x)); return y;
}
__device__ __forceinline__ float sigm(float x) {
    // 1/(1+exp(-x)); MUFU EX2+RCP, abs err ~1e-6, saturates correctly at +/-inf
    return rcpf(1.0f + ex2f(-1.4426950408889634f * x));
}
__device__ __forceinline__ float tanhx(float x) {
    // 2/(1+exp(-2x)) - 1
    return fmaf(2.0f, rcpf(1.0f + ex2f(-2.8853900817779268f * x)), -1.0f);
}

// ---------------------------------------------------------------------------
// Rank-1-update GEMM slice over K features for this thread's 4 gate columns.
// Inputs k-major in SMEM (broadcast LDS.64 row pairs); weights ring-prefetched
// PF=4 deep to cover L2 latency (~262 cyc < 4 * 64 cyc/k-iter).
// ---------------------------------------------------------------------------
__device__ __forceinline__ void gemm_acc(const float4* __restrict__ w,
                                         unsigned s, int K, ull acc[4][BB/2])
{
    float4 wb0 = __ldg(w);
    float4 wb1 = __ldg(w + 256);
    float4 wb2 = __ldg(w + 2 * 256);
    float4 wb3 = __ldg(w + 3 * 256);
#pragma unroll 4
    for (int k = 0; k < K; ++k) {
        float4 wc = wb0;
        wb0 = wb1; wb1 = wb2; wb2 = wb3;
        wb3 = __ldg(w + (k + PF) * 256);          // zero pad rows make this safe
        ull d0 = dupf(wc.x), d1 = dupf(wc.y), d2 = dupf(wc.z), d3 = dupf(wc.w);
        unsigned sk = s + (unsigned)(k * PAD * 4);
#pragma unroll
        for (int p = 0; p < BB / 2; ++p) {
            ull a = lds64(sk + p * 8);            // rows (2p, 2p+1) packed f32x2
            acc[0][p] = fma2(a, d0, acc[0][p]);
            acc[1][p] = fma2(a, d1, acc[1][p]);
            acc[2][p] = fma2(a, d2, acc[2][p]);
            acc[3][p] = fma2(a, d3, acc[3][p]);
        }
    }
}

// ---------------------------------------------------------------------------
// Persistent kernel: 148 blocks. Static LPT over 256 length-sorted groups:
//   blocks 0..39    -> single group b          (longest groups)
//   blocks 40..147  -> groups {b, 295-b}       (balanced duration pairs)
// Thread tid owns h-index n=tid (4 gates) for all 8 rows of the group.
// ---------------------------------------------------------------------------
__global__ __launch_bounds__(NTHREADS, 1)
void lstm_kernel(const float* __restrict__ x, const int* __restrict__ lengths,
                 const float* __restrict__ Wout, const float* __restrict__ bout,
                 float* __restrict__ out)
{
    __shared__ __align__(16) float x_s[Fdim * PAD];    // k-major: x_s[k*PAD + r]
    __shared__ __align__(16) float h1_s[Hdim * PAD];
    __shared__ __align__(16) float h2_s[Hdim * PAD];
    __shared__ int   len_s[BB];
    __shared__ int   perm_s[BB];

    const int tid = threadIdx.x;
    const int blk = blockIdx.x;

    const unsigned xsa = (unsigned)__cvta_generic_to_shared(x_s);
    const unsigned h1a = (unsigned)__cvta_generic_to_shared(h1_s);
    const unsigned h2a = (unsigned)__cvta_generic_to_shared(h2_s);

    const float4* W1p4 = reinterpret_cast<const float4*>(g_W1p);
    const float4* W2p4 = reinterpret_cast<const float4*>(g_W2p);
    const float4  b1v  = reinterpret_cast<const float4*>(g_b1p)[tid];
    const float4  b2v  = reinterpret_cast<const float4*>(g_b2p)[tid];

    const int kx = tid & 127;      // x staging: feature index
    const int ph = tid >> 7;       // row parity this thread stages

    int glist[2];
    int ng;
    if (blk < NSINGLE) { glist[0] = blk; ng = 1; }
    else               { glist[0] = blk; glist[1] = (NGRP - 1 + NSINGLE) - blk; ng = 2; }

    for (int gi = 0; gi < ng; ++gi) {
        const int grp = glist[gi];

        // ---- per-group init ----
        __syncthreads();   // previous group fully done with smem
        for (int i = tid; i < Hdim * PAD; i += NTHREADS) { h1_s[i] = 0.0f; h2_s[i] = 0.0f; }
        if (tid < BB) {
            int p = g_perm[grp * BB + tid];
            perm_s[tid] = p;
            len_s[tid]  = __ldg(&lengths[p]);
        }
        __syncthreads();
        const int tmax = len_s[0];             // descending sort: row 0 is max

        float c1[BB], c2[BB], sum[BB];
#pragma unroll
        for (int r = 0; r < BB; ++r) { c1[r] = 0.0f; c2[r] = 0.0f; sum[r] = 0.0f; }

        for (int t = 0; t < tmax; ++t) {
            // ---- stage x_t into k-major SMEM (coalesced within each row) ----
#pragma unroll
            for (int j = 0; j < BB / 2; ++j) {
                int r = 2 * j + ph;                       // rows 0..7
                x_s[kx * PAD + r] =
                    __ldg(x + (size_t)perm_s[r] * (Tlen * Fdim) + t * Fdim + kx);
            }
            __syncthreads();                   // x ready, prev-step h2 visible

            // ---- layer 1 GEMM: z = [x_t | h1] @ W1p + b1p ----
            ull acc[4][BB / 2];
#pragma unroll
            for (int p = 0; p < BB / 2; ++p) {
                acc[0][p] = dupf(b1v.x); acc[1][p] = dupf(b1v.y);
                acc[2][p] = dupf(b1v.z); acc[3][p] = dupf(b1v.w);
            }
            gemm_acc(W1p4 + tid,              xsa, Fdim, acc);
            gemm_acc(W1p4 + Fdim * 256 + tid, h1a, Hdim, acc);
            __syncthreads();                   // everyone done reading h1_s

            // ---- layer 1 cell update (registers; n = tid) ----
#pragma unroll
            for (int p = 0; p < BB / 2; ++p) {
                float2 iv = unpk(acc[0][p]), jv = unpk(acc[1][p]);
                float2 fv = unpk(acc[2][p]), ov = unpk(acc[3][p]);
                {
                    int r = 2 * p;
                    if (t < len_s[r]) {
                        float nc = c1[r] * sigm(fv.x + 1.0f) + sigm(iv.x) * tanhx(jv.x);
                        c1[r] = nc;
                        h1_s[tid * PAD + r] = tanhx(nc) * sigm(ov.x);
                    }
                }
                {
                    int r = 2 * p + 1;
                    if (t < len_s[r]) {
                        float nc = c1[r] * sigm(fv.y + 1.0f) + sigm(iv.y) * tanhx(jv.y);
                        c1[r] = nc;
                        h1_s[tid * PAD + r] = tanhx(nc) * sigm(ov.y);
                    }
                }
            }
            __syncthreads();                   // new h1 visible

            // ---- layer 2 GEMM: z = [h1 | h2] @ W2p + b2p ----
#pragma unroll
            for (int p = 0; p < BB / 2; ++p) {
                acc[0][p] = dupf(b2v.x); acc[1][p] = dupf(b2v.y);
                acc[2][p] = dupf(b2v.z); acc[3][p] = dupf(b2v.w);
            }
            gemm_acc(W2p4 + tid,              h1a, Hdim, acc);
            gemm_acc(W2p4 + Hdim * 256 + tid, h2a, Hdim, acc);
            __syncthreads();                   // everyone done reading h2_s

            // ---- layer 2 cell update + masked output accumulation ----
#pragma unroll
            for (int p = 0; p < BB / 2; ++p) {
                float2 iv = unpk(acc[0][p]), jv = unpk(acc[1][p]);
                float2 fv = unpk(acc[2][p]), ov = unpk(acc[3][p]);
                {
                    int r = 2 * p;
                    if (t < len_s[r]) {
                        float nc = c2[r] * sigm(fv.x + 1.0f) + sigm(iv.x) * tanhx(jv.x);
                        c2[r] = nc;
                        float nh = tanhx(nc) * sigm(ov.x);
                        h2_s[tid * PAD + r] = nh;
                        sum[r] += nh;
                    }
                }
                {
                    int r = 2 * p + 1;
                    if (t < len_s[r]) {
                        float nc = c2[r] * sigm(fv.y + 1.0f) + sigm(iv.y) * tanhx(jv.y);
                        c2[r] = nc;
                        float nh = tanhx(nc) * sigm(ov.y);
                        h2_s[tid * PAD + r] = nh;
                        sum[r] += nh;
                    }
                }
            }
            // no barrier: next-iter barriers order h2 writes vs reads
        }

        // ---- epilogue: avg over valid steps, project to O=6 logits ----
#pragma unroll
        for (int r = 0; r < BB; ++r)
            h1_s[tid * PAD + r] = sum[r] / (float)len_s[r];   // scratch reuse
        __syncthreads();

        if (tid < BB * Odim) {
            int r = tid / Odim, o = tid % Odim;
            float a = __ldg(&bout[o]);
            for (int n = 0; n < Hdim; ++n)
                a += h1_s[n * PAD + r] * __ldg(&Wout[n * Odim + o]);
            out[perm_s[r] * Odim + o] = a;
        }
    }
}

// ---------------------------------------------------------------------------
// Launch
// ---------------------------------------------------------------------------
extern "C" void kernel_launch(void* const* d_in, const int* in_sizes, int n_in,
                              void* d_out, int out_size)
{
    const float* x       = (const float*)d_in[0];
    const int*   lengths = (const int*)  d_in[1];
    const float* W1      = (const float*)d_in[2];
    const float* b1      = (const float*)d_in[3];
    const float* W2      = (const float*)d_in[4];
    const float* b2      = (const float*)d_in[5];
    const float* Wout    = (const float*)d_in[6];
    const float* bout    = (const float*)d_in[7];
    float*       out     = (float*)d_out;

    permute_kernel<<<((Fdim + Hdim + PF) * G4H + NTHREADS - 1) / NTHREADS, NTHREADS>>>(
        W1, b1, Fdim + Hdim, 0);
    permute_kernel<<<((2 * Hdim + PF) * G4H + NTHREADS - 1) / NTHREADS, NTHREADS>>>(
        W2, b2, 2 * Hdim, 1);
    rank_kernel<<<Bsz / NTHREADS, NTHREADS>>>(lengths);

    lstm_kernel<<<NSM, NTHREADS>>>(x, lengths, Wout, bout, out);
}